// round 10
// baseline (speedup 1.0000x reference)
#include <cuda_runtime.h>
#include <cstdint>

// Problem constants (from reference)
#define GB_T 1000000
#define GB_C 16
#define GB_G 500000
#define GB_K 9
#define GB_GK (GB_G * GB_K)              // 4,500,000 (g,k) rows
#define GB_CH_PER_B (GB_GK * 2)          // 9,000,000 32-byte chunks per batch
#define GB_UNROLL 4
#define GB_STRIDE (GB_CH_PER_B / GB_UNROLL)  // 2,250,000 (exact)

// 256-bit gather load with L2 evict-last (sm_103 requires .v4.b64/.v8.b32 for
// the evict_last modifier). Texture lines stay resident while the never-re-read
// output stream goes through evict-first stores.
__device__ __forceinline__ void ldg256_evict_last(const void* p, unsigned long long r[4]) {
    asm volatile("ld.global.nc.L2::evict_last.v4.u64 {%0,%1,%2,%3}, [%4];"
                 : "=l"(r[0]), "=l"(r[1]), "=l"(r[2]), "=l"(r[3])
                 : "l"(p));
}

__device__ __forceinline__ void stg128_cs(void* p, unsigned long long a, unsigned long long b) {
    asm volatile("st.global.cs.v2.u64 [%0], {%1,%2};"
                 :: "l"(p), "l"(a), "l"(b) : "memory");
}

__global__ __launch_bounds__(256)
void gather_groups_kernel(const char* __restrict__ tex,    // [B, T*64] bytes
                          const int*  __restrict__ gidx,   // [G*K]
                          char*       __restrict__ out)    // [B, G*K*64] bytes
{
    const int tid = blockIdx.x * blockDim.x + threadIdx.x;
    if (tid >= GB_STRIDE) return;
    const int b = blockIdx.y;

    const char* tex_b = tex + (int64_t)b * ((int64_t)GB_T * 64);
    char*       out_b = out + (int64_t)b * ((int64_t)GB_GK * 64);

    // Front-batch 4 independent index loads (2 threads share one idx)
    int idx[GB_UNROLL];
#pragma unroll
    for (int u = 0; u < GB_UNROLL; u++) {
        const int e = tid + u * GB_STRIDE;            // 32B-chunk id
        idx[u] = __ldg(&gidx[e >> 1]);
    }

    // Front-batch 4 independent 256-bit gathers (128B in flight/thread), evict-last
    unsigned long long v[GB_UNROLL][4];
#pragma unroll
    for (int u = 0; u < GB_UNROLL; u++) {
        const int e  = tid + u * GB_STRIDE;
        const int c2 = e & 1;                         // which 32B half of the 64B row
        ldg256_evict_last(tex_b + (int64_t)idx[u] * 64 + c2 * 32, v[u]);
    }

    // Evict-first streaming stores (two 16B stores per 32B chunk), coalesced
#pragma unroll
    for (int u = 0; u < GB_UNROLL; u++) {
        const int e = tid + u * GB_STRIDE;
        char* dst = out_b + (int64_t)e * 32;
        stg128_cs(dst,      v[u][0], v[u][1]);
        stg128_cs(dst + 16, v[u][2], v[u][3]);
    }
}

extern "C" void kernel_launch(void* const* d_in, const int* in_sizes, int n_in,
                              void* d_out, int out_size) {
    // metadata order: mesh_ids (int32 [B]) — unused by reference math,
    //                 textures (float32 [B,T,C]), group_idx (int32 [G,K])
    const char* tex  = (const char*)d_in[1];
    const int*  gidx = (const int*)d_in[2];
    char*       out  = (char*)d_out;

    const int threads = 256;
    const int blocks = (GB_STRIDE + threads - 1) / threads;  // 8790
    dim3 grid(blocks, 2, 1);  // grid.y = B (b=0 blocks raster first -> mostly batch-serial L2 use)

    gather_groups_kernel<<<grid, threads>>>(tex, gidx, out);
}